// round 13
// baseline (speedup 1.0000x reference)
#include <cuda_runtime.h>
#include <math.h>

#define NNODES 30000
#define DIM    128
#define TLINKS 3000
#define KNEG   75
#define GAMMA  1.0f
#define MAXSQ  50.0f
// float(1.0 + 1e-7) == 0x3F800001 (1 ulp above 1.0f) — matches XLA's f32 cast
#define THETA0 (1.0f + 1e-7f)
#define FBGRID 128

// ---- device scratch (no allocation allowed) ----
__device__ double       g_part[TLINKS];    // per-link fast-path contribution
__device__ float        g_D[TLINKS];       // per-link D = sqdist(l,r)+GAMMA
__device__ int          g_queue[2*TLINKS]; // flagged query ids (side*TLINKS+t)
__device__ int          g_nfb    = 0;      // queue length; reset by fb finisher
__device__ double       g_fbsum  = 0.0;    // fallback sum;  reset by fb finisher
__device__ double       g_partsum = 0.0;   // fast-path total (for fb finisher)
__device__ unsigned int g_ticket_hot = 0;  // wraps mod TLINKS each replay
__device__ unsigned int g_ticket_fb  = 0;  // used only when queue non-empty

// ---------------------------------------------------------------------------
__device__ __forceinline__ float sqdist_from_mdot(float mdot, float cval, float Kv) {
    float th = fmaxf(-mdot * cval, THETA0);
    float a  = acoshf(th);
    return fminf(Kv * a * a, MAXSQ);
}

// full 128-dim Minkowski sqdist, one thread (fallback path only)
__device__ __forceinline__ float sqdist_full(const float* __restrict__ q,
                                             const float* __restrict__ row,
                                             float cval, float Kv) {
    float md = 0.f;
#pragma unroll
    for (int d = 0; d < DIM; d++) {
        float p = q[d] * row[d];
        md += (d == 0) ? -p : p;
    }
    return sqdist_from_mdot(md, cval, Kv);
}

// ---------------------------------------------------------------------------
// Per-row dot pair with split accumulators (8-deep FFMA chains).
// Returns via s0/s1 the FULL (sub-group-reduced) dots on every lane.
template <bool GUARD>
__device__ __forceinline__ void row_dots(const float* __restrict__ emb, int row,
                                         const float4* a0, const float4* a1, int sub,
                                         float& s0, float& s1) {
    float s0a = 0.f, s0b = 0.f, s1a = 0.f, s1b = 0.f;
    if (!GUARD || row < NNODES) {
        const float4* p = (const float4*)(emb + (size_t)row * DIM);
        float4 y0 = p[0 * 8 + sub];
        float4 y1 = p[1 * 8 + sub];
        float4 y2 = p[2 * 8 + sub];
        float4 y3 = p[3 * 8 + sub];
        s0a = a0[0].x*y0.x + a0[0].y*y0.y + a0[0].z*y0.z + a0[0].w*y0.w
            + a0[1].x*y1.x + a0[1].y*y1.y + a0[1].z*y1.z + a0[1].w*y1.w;
        s0b = a0[2].x*y2.x + a0[2].y*y2.y + a0[2].z*y2.z + a0[2].w*y2.w
            + a0[3].x*y3.x + a0[3].y*y3.y + a0[3].z*y3.z + a0[3].w*y3.w;
        s1a = a1[0].x*y0.x + a1[0].y*y0.y + a1[0].z*y0.z + a1[0].w*y0.w
            + a1[1].x*y1.x + a1[1].y*y1.y + a1[1].z*y1.z + a1[1].w*y1.w;
        s1b = a1[2].x*y2.x + a1[2].y*y2.y + a1[2].z*y2.z + a1[2].w*y2.w
            + a1[3].x*y3.x + a1[3].y*y3.y + a1[3].z*y3.z + a1[3].w*y3.w;
    } else {
        s0a = -1e30f; s1a = -1e30f;    // guarded-out rows never count
    }
    s0 = s0a + s0b;
    s1 = s1a + s1b;
    s0 += __shfl_xor_sync(0xffffffffu, s0, 1);
    s1 += __shfl_xor_sync(0xffffffffu, s1, 1);
    s0 += __shfl_xor_sync(0xffffffffu, s0, 2);
    s1 += __shfl_xor_sync(0xffffffffu, s1, 2);
    s0 += __shfl_xor_sync(0xffffffffu, s0, 4);
    s1 += __shfl_xor_sync(0xffffffffu, s1, 4);
}

// ---------------------------------------------------------------------------
// HOT kernel: one block (256 threads) per link; 4 blocks/SM.
//  - is64 detected per-warp (warps 0/1) by a 32-sample ballot over odd int32
//    words (int64 ids < 30000 have all odd words zero).
//  - coalesced candidate reads: lane sub owns float4s j = i*8+sub.
//  - count rows with theta clipped (mdot >= -THETA0/c <=> sqdist == S0);
//    count >= 75  =>  top-75 all exactly S0  =>  75 * relu(D - S0).
//    Else (never in practice): push query onto the fallback work-queue.
//  - LAST block (wrap ticket) reduces g_part, stores g_partsum, writes out.
//    That value is final whenever the queue is empty; otherwise the fallback
//    kernel (which runs after) overwrites out with the corrected total.
__global__ void __launch_bounds__(256, 4) hot_kernel(const float* __restrict__ emb,
                                                     const float* __restrict__ cptr,
                                                     const void*  __restrict__ links,
                                                     float*       __restrict__ out) {
    __shared__ float  q[2][DIM];
    __shared__ float  sD;
    __shared__ int    sc0, sc1;
    __shared__ int    s_last;
    __shared__ double sred[256];

    const int t    = blockIdx.x;
    const int tid  = threadIdx.x;
    const int w    = tid >> 5;
    const int lane = tid & 31;
    const int sub  = lane & 7;          // 8-lane sub-group position

    const float cval = cptr[0];
    const float Kv   = 1.0f / cval;

    // warps 0/1: detect dtype, fetch own node, stage its q row (float4)
    if (w < 2) {
        const int* links32 = (const int*)links;
        int idx = t + lane; if (idx >= TLINKS) idx -= TLINKS;
        unsigned nz = __ballot_sync(0xffffffffu, links32[2 * idx + 1] != 0);
        const int is64 = (nz == 0);
        long long node = is64 ? ((const long long*)links)[2 * t + w]
                              : (long long)links32[2 * t + w];
        ((float4*)q[w])[lane] = ((const float4*)(emb + (size_t)node * DIM))[lane];
    }
    if (tid == 0) { sc0 = 0; sc1 = 0; }
    __syncthreads();

    // per-lane register slices, mapping j = i*8 + sub (dim 0 is i=0,sub=0,.x)
    float4 a0[4], a1[4];
#pragma unroll
    for (int i = 0; i < 4; i++) {
        a0[i] = ((const float4*)q[0])[i * 8 + sub];
        a1[i] = ((const float4*)q[1])[i * 8 + sub];
    }
    if (sub == 0) { a0[0].x = -a0[0].x; a1[0].x = -a1[0].x; }

    // D = sqdist(left,right) + GAMMA  (sign-folded a0 vs RAW q1)
    if (w == 0) {
        float s = 0.f;
#pragma unroll
        for (int i = 0; i < 4; i++) {
            float4 b = ((const float4*)q[1])[i * 8 + sub];
            s += a0[i].x * b.x + a0[i].y * b.y + a0[i].z * b.z + a0[i].w * b.w;
        }
        s += __shfl_xor_sync(0xffffffffu, s, 1);
        s += __shfl_xor_sync(0xffffffffu, s, 2);
        s += __shfl_xor_sync(0xffffffffu, s, 4);
        if (tid == 0) sD = sqdist_from_mdot(s, cval, Kv) + GAMMA;
    }
    __syncthreads();
    const float D = sD;

    float acz = acoshf(THETA0);
    const float S0  = fminf(Kv * acz * acz, MAXSQ);
    const float thr = -(THETA0 * Kv);    // mdot >= thr  <=>  theta clips to 1+EPS

    const int rbase0 = (w << 5) + (lane >> 3);
    int l0 = 0, l1 = 0;

    // ---- chunk 0: rows 0..255, no bounds guard (256 << NNODES) ----
#pragma unroll 4
    for (int g = 0; g < 8; g++) {
        float s0, s1;
        row_dots<false>(emb, rbase0 + g * 4, a0, a1, sub, s0, s1);
        l0 += (s0 >= thr);
        l1 += (s1 >= thr);
    }
    // xor8 + xor16 -> exact warp count on every lane.
    l0 += __shfl_xor_sync(0xffffffffu, l0, 8);
    l1 += __shfl_xor_sync(0xffffffffu, l1, 8);
    l0 += __shfl_xor_sync(0xffffffffu, l0, 16);
    l1 += __shfl_xor_sync(0xffffffffu, l1, 16);
    if (lane == 0) { atomicAdd(&sc0, l0); atomicAdd(&sc1, l1); }
    __syncthreads();
    int c0 = sc0, c1 = sc1;
    __syncthreads();

    // ---- rare continuation: more chunks until both counts reach 75 ----
    int base = 256;
    while (base < NNODES && (c0 < KNEG || c1 < KNEG)) {
        int m0 = 0, m1 = 0;
#pragma unroll 2
        for (int g = 0; g < 8; g++) {
            float s0, s1;
            row_dots<true>(emb, base + rbase0 + g * 4, a0, a1, sub, s0, s1);
            m0 += (s0 >= thr);
            m1 += (s1 >= thr);
        }
        m0 += __shfl_xor_sync(0xffffffffu, m0, 8);
        m1 += __shfl_xor_sync(0xffffffffu, m1, 8);
        m0 += __shfl_xor_sync(0xffffffffu, m0, 16);
        m1 += __shfl_xor_sync(0xffffffffu, m1, 16);
        if (lane == 0) { atomicAdd(&sc0, m0); atomicAdd(&sc1, m1); }
        __syncthreads();
        c0 = sc0; c1 = sc1;
        __syncthreads();
        base += 256;
    }

    if (tid == 0) {
        double fast = (double)KNEG * (double)fmaxf(D - S0, 0.f);
        double contrib = 0.0;
        if (c0 >= KNEG) contrib += fast;
        if (c1 >= KNEG) contrib += fast;
        g_part[t] = contrib;
        g_D[t]    = D;
        if (c0 < KNEG) g_queue[atomicAdd(&g_nfb, 1)] = t;            // side 0
        if (c1 < KNEG) g_queue[atomicAdd(&g_nfb, 1)] = TLINKS + t;   // side 1
    }

    // ---- ticket: last block reduces g_part and writes the output ----
    if (tid == 0) {
        __threadfence();
        unsigned int old = atomicInc(&g_ticket_hot, TLINKS - 1);  // wraps to 0
        s_last = (old == TLINKS - 1);
    }
    __syncthreads();

    if (s_last) {
        __threadfence();
        const volatile double* vp = g_part;
        double sum = 0.0;
        for (int i = tid; i < TLINKS; i += 256) sum += vp[i];
        sred[tid] = sum;
        __syncthreads();
        for (int o = 128; o > 0; o >>= 1) {
            if (tid < o) sred[tid] += sred[tid + o];
            __syncthreads();
        }
        if (tid == 0) {
            g_partsum = sred[0];
            out[0] = (float)(sred[0] / (2.0 * (double)KNEG * (double)TLINKS));
        }
    }
}

// ---------------------------------------------------------------------------
// Fallback guard: if the work queue is empty (always, in practice) every
// block exits immediately — cost is bare kernel launch/exit. Otherwise run
// the exact MSB-first radix select per flagged query, and the last-ticket
// block overwrites out with g_partsum + fbsum and resets the queue state.
__global__ void __launch_bounds__(256) fallback_kernel(const float* __restrict__ emb,
                                                       const float* __restrict__ cptr,
                                                       const void*  __restrict__ links,
                                                       float*       __restrict__ out) {
    const int nfb = g_nfb;   // written by hot_kernel (kernel-boundary visible)
    if (nfb == 0) return;    // uniform: whole grid exits

    const int tid = threadIdx.x;

    __shared__ float        q[DIM];
    __shared__ unsigned int hist[256];
    __shared__ unsigned int s_prefix;
    __shared__ int          s_k;
    __shared__ double       ssum[256];
    __shared__ int          scm[256];
    __shared__ int          s_last;

    for (int qi = blockIdx.x; qi < nfb; qi += FBGRID) {
        const int s    = g_queue[qi];
        const int t    = s % TLINKS;
        const int side = s / TLINKS;

        const float cval = cptr[0];
        const float Kv   = 1.0f / cval;
        const int* links32 = (const int*)links;

        // dtype detection (32 odd-word samples, block-wide OR)
        int mybad = 0;
        if (tid < 32) {
            int idx = t + tid; if (idx >= TLINKS) idx -= TLINKS;
            mybad = (links32[2 * idx + 1] != 0);
        }
        const int is64 = __syncthreads_or(mybad) ? 0 : 1;

        const long long node = is64 ? ((const long long*)links)[2 * t + side]
                                    : (long long)links32[2 * t + side];

        if (tid < DIM) q[tid] = emb[(size_t)node * DIM + tid];
        if (tid == 0) { s_prefix = 0u; s_k = KNEG; }
        __syncthreads();

        const float D = g_D[t];

        for (int pass = 0; pass < 4; pass++) {
            const int shift = 24 - 8 * pass;
            const unsigned int pmask  = (pass == 0) ? 0u : (0xFFFFFFFFu << (shift + 8));
            const unsigned int prefix = s_prefix;
            hist[tid] = 0u;
            __syncthreads();
            for (int j = tid; j < NNODES; j += 256) {
                float v = sqdist_full(q, emb + (size_t)j * DIM, cval, Kv);
                unsigned int b = __float_as_uint(v);
                if ((b & pmask) == prefix)
                    atomicAdd(&hist[(b >> shift) & 0xFFu], 1u);
            }
            __syncthreads();
            if (tid == 0) {
                int k = s_k;
                unsigned int acc = 0;
                int digit = 0;
                for (; digit < 255; digit++) {
                    if (acc + hist[digit] >= (unsigned)k) break;
                    acc += hist[digit];
                }
                s_k      = k - (int)acc;
                s_prefix = prefix | ((unsigned)digit << shift);
            }
            __syncthreads();
        }

        const unsigned int tau_bits = s_prefix;
        const float        tau      = __uint_as_float(tau_bits);

        int    m_local = 0;
        double sum_local = 0.0;
        for (int j = tid; j < NNODES; j += 256) {
            float v = sqdist_full(q, emb + (size_t)j * DIM, cval, Kv);
            if (__float_as_uint(v) < tau_bits) {
                m_local++;
                sum_local += (double)fmaxf(D - v, 0.f);
            }
        }
        ssum[tid] = sum_local;
        scm[tid]  = m_local;
        __syncthreads();
        for (int o = 128; o > 0; o >>= 1) {
            if (tid < o) { ssum[tid] += ssum[tid + o]; scm[tid] += scm[tid + o]; }
            __syncthreads();
        }
        if (tid == 0) {
            int m = scm[0];
            double res = ssum[0] + (double)(KNEG - m) * (double)fmaxf(D - tau, 0.f);
            atomicAdd(&g_fbsum, res);
        }
        __syncthreads();
    }

    // ---- ticket (only reached when nfb > 0): last block finalizes ----
    if (tid == 0) {
        __threadfence();
        unsigned int old = atomicInc(&g_ticket_fb, FBGRID - 1);  // wraps to 0
        s_last = (old == FBGRID - 1);
    }
    __syncthreads();

    if (s_last && tid == 0) {
        __threadfence();
        double total = g_partsum + g_fbsum;
        out[0] = (float)(total / (2.0 * (double)KNEG * (double)TLINKS));
        g_nfb   = 0;      // reset queue state for the next graph replay
        g_fbsum = 0.0;
    }
}

// ---------------------------------------------------------------------------
extern "C" void kernel_launch(void* const* d_in, const int* in_sizes, int n_in,
                              void* d_out, int out_size) {
    const float* emb   = nullptr;
    const float* c     = nullptr;
    const void*  links = nullptr;
    for (int i = 0; i < n_in; i++) {
        if (in_sizes[i] == 1)               c     = (const float*)d_in[i];
        else if (in_sizes[i] == 2 * TLINKS) links = d_in[i];
        else                                emb   = (const float*)d_in[i];
    }

    hot_kernel     <<<TLINKS, 256>>>(emb, c, links, (float*)d_out);
    fallback_kernel<<<FBGRID, 256>>>(emb, c, links, (float*)d_out);
}

// round 14
// speedup vs baseline: 1.6652x; 1.6652x over previous
#include <cuda_runtime.h>
#include <math.h>

#define NNODES 30000
#define DIM    128
#define TLINKS 3000
#define KNEG   75
#define GAMMA  1.0f
#define MAXSQ  50.0f
// float(1.0 + 1e-7) == 0x3F800001 (1 ulp above 1.0f) — matches XLA's f32 cast
#define THETA0 (1.0f + 1e-7f)
#define FBGRID 128

// ---- device scratch (no allocation allowed) ----
__device__ double       g_acc    = 0.0;    // fast-path sum; reset by hot finisher
__device__ double       g_partsum = 0.0;   // snapshot for fb finisher
__device__ float        g_D[TLINKS];       // per-link D = sqdist(l,r)+GAMMA
__device__ int          g_queue[2*TLINKS]; // flagged query ids (side*TLINKS+t)
__device__ int          g_nfb    = 0;      // queue length; reset by fb finisher
__device__ double       g_fbsum  = 0.0;    // fallback sum;  reset by fb finisher
__device__ unsigned int g_ticket_hot = 0;  // wraps mod TLINKS each replay
__device__ unsigned int g_ticket_fb  = 0;  // used only when queue non-empty

// ---------------------------------------------------------------------------
__device__ __forceinline__ float sqdist_from_mdot(float mdot, float cval, float Kv) {
    float th = fmaxf(-mdot * cval, THETA0);
    float a  = acoshf(th);
    return fminf(Kv * a * a, MAXSQ);
}

// full 128-dim Minkowski sqdist, one thread (fallback path only)
__device__ __forceinline__ float sqdist_full(const float* __restrict__ q,
                                             const float* __restrict__ row,
                                             float cval, float Kv) {
    float md = 0.f;
#pragma unroll
    for (int d = 0; d < DIM; d++) {
        float p = q[d] * row[d];
        md += (d == 0) ? -p : p;
    }
    return sqdist_from_mdot(md, cval, Kv);
}

// ---------------------------------------------------------------------------
// Per-row dot pair with split accumulators (8-deep FFMA chains).
// Returns via s0/s1 the FULL (sub-group-reduced) dots on every lane.
template <bool GUARD>
__device__ __forceinline__ void row_dots(const float* __restrict__ emb, int row,
                                         const float4* a0, const float4* a1, int sub,
                                         float& s0, float& s1) {
    float s0a = 0.f, s0b = 0.f, s1a = 0.f, s1b = 0.f;
    if (!GUARD || row < NNODES) {
        const float4* p = (const float4*)(emb + (size_t)row * DIM);
        float4 y0 = p[0 * 8 + sub];
        float4 y1 = p[1 * 8 + sub];
        float4 y2 = p[2 * 8 + sub];
        float4 y3 = p[3 * 8 + sub];
        s0a = a0[0].x*y0.x + a0[0].y*y0.y + a0[0].z*y0.z + a0[0].w*y0.w
            + a0[1].x*y1.x + a0[1].y*y1.y + a0[1].z*y1.z + a0[1].w*y1.w;
        s0b = a0[2].x*y2.x + a0[2].y*y2.y + a0[2].z*y2.z + a0[2].w*y2.w
            + a0[3].x*y3.x + a0[3].y*y3.y + a0[3].z*y3.z + a0[3].w*y3.w;
        s1a = a1[0].x*y0.x + a1[0].y*y0.y + a1[0].z*y0.z + a1[0].w*y0.w
            + a1[1].x*y1.x + a1[1].y*y1.y + a1[1].z*y1.z + a1[1].w*y1.w;
        s1b = a1[2].x*y2.x + a1[2].y*y2.y + a1[2].z*y2.z + a1[2].w*y2.w
            + a1[3].x*y3.x + a1[3].y*y3.y + a1[3].z*y3.z + a1[3].w*y3.w;
    } else {
        s0a = -1e30f; s1a = -1e30f;    // guarded-out rows never count
    }
    s0 = s0a + s0b;
    s1 = s1a + s1b;
    s0 += __shfl_xor_sync(0xffffffffu, s0, 1);
    s1 += __shfl_xor_sync(0xffffffffu, s1, 1);
    s0 += __shfl_xor_sync(0xffffffffu, s0, 2);
    s1 += __shfl_xor_sync(0xffffffffu, s1, 2);
    s0 += __shfl_xor_sync(0xffffffffu, s0, 4);
    s1 += __shfl_xor_sync(0xffffffffu, s1, 4);
}

// ---------------------------------------------------------------------------
// HOT kernel: one block (256 threads) per link; 4 blocks/SM.
//  - is64 detected per-warp (warps 0/1) by a 32-sample ballot over odd int32
//    words (int64 ids < 30000 have all odd words zero).
//  - coalesced candidate reads: lane sub owns float4s j = i*8+sub.
//  - count rows with theta clipped (mdot >= -THETA0/c <=> sqdist == S0);
//    count >= 75  =>  top-75 all exactly S0  =>  75 * relu(D - S0).
//    Else (never in practice): push query onto the fallback work-queue.
//  - contribution accumulated via ONE fp64 atomicAdd per block (no array,
//    no reduction tail — keeps the register budget clean). The last-ticket
//    block reads g_acc, writes out, snapshots g_partsum, resets g_acc.
__global__ void __launch_bounds__(256, 4) hot_kernel(const float* __restrict__ emb,
                                                     const float* __restrict__ cptr,
                                                     const void*  __restrict__ links,
                                                     float*       __restrict__ out) {
    __shared__ float  q[2][DIM];
    __shared__ float  sD;
    __shared__ int    sc0, sc1;

    const int t    = blockIdx.x;
    const int tid  = threadIdx.x;
    const int w    = tid >> 5;
    const int lane = tid & 31;
    const int sub  = lane & 7;          // 8-lane sub-group position

    const float cval = cptr[0];
    const float Kv   = 1.0f / cval;

    // warps 0/1: detect dtype, fetch own node, stage its q row (float4)
    if (w < 2) {
        const int* links32 = (const int*)links;
        int idx = t + lane; if (idx >= TLINKS) idx -= TLINKS;
        unsigned nz = __ballot_sync(0xffffffffu, links32[2 * idx + 1] != 0);
        const int is64 = (nz == 0);
        long long node = is64 ? ((const long long*)links)[2 * t + w]
                              : (long long)links32[2 * t + w];
        ((float4*)q[w])[lane] = ((const float4*)(emb + (size_t)node * DIM))[lane];
    }
    if (tid == 0) { sc0 = 0; sc1 = 0; }
    __syncthreads();

    // per-lane register slices, mapping j = i*8 + sub (dim 0 is i=0,sub=0,.x)
    float4 a0[4], a1[4];
#pragma unroll
    for (int i = 0; i < 4; i++) {
        a0[i] = ((const float4*)q[0])[i * 8 + sub];
        a1[i] = ((const float4*)q[1])[i * 8 + sub];
    }
    if (sub == 0) { a0[0].x = -a0[0].x; a1[0].x = -a1[0].x; }

    // D = sqdist(left,right) + GAMMA  (sign-folded a0 vs RAW q1)
    if (w == 0) {
        float s = 0.f;
#pragma unroll
        for (int i = 0; i < 4; i++) {
            float4 b = ((const float4*)q[1])[i * 8 + sub];
            s += a0[i].x * b.x + a0[i].y * b.y + a0[i].z * b.z + a0[i].w * b.w;
        }
        s += __shfl_xor_sync(0xffffffffu, s, 1);
        s += __shfl_xor_sync(0xffffffffu, s, 2);
        s += __shfl_xor_sync(0xffffffffu, s, 4);
        if (tid == 0) sD = sqdist_from_mdot(s, cval, Kv) + GAMMA;
    }
    __syncthreads();
    const float D = sD;

    float acz = acoshf(THETA0);
    const float S0  = fminf(Kv * acz * acz, MAXSQ);
    const float thr = -(THETA0 * Kv);    // mdot >= thr  <=>  theta clips to 1+EPS

    const int rbase0 = (w << 5) + (lane >> 3);
    int l0 = 0, l1 = 0;

    // ---- chunk 0: rows 0..255, no bounds guard (256 << NNODES) ----
#pragma unroll 4
    for (int g = 0; g < 8; g++) {
        float s0, s1;
        row_dots<false>(emb, rbase0 + g * 4, a0, a1, sub, s0, s1);
        l0 += (s0 >= thr);
        l1 += (s1 >= thr);
    }
    // xor8 + xor16 -> exact warp count on every lane.
    l0 += __shfl_xor_sync(0xffffffffu, l0, 8);
    l1 += __shfl_xor_sync(0xffffffffu, l1, 8);
    l0 += __shfl_xor_sync(0xffffffffu, l0, 16);
    l1 += __shfl_xor_sync(0xffffffffu, l1, 16);
    if (lane == 0) { atomicAdd(&sc0, l0); atomicAdd(&sc1, l1); }
    __syncthreads();
    int c0 = sc0, c1 = sc1;
    __syncthreads();

    // ---- rare continuation: more chunks until both counts reach 75 ----
    int base = 256;
    while (base < NNODES && (c0 < KNEG || c1 < KNEG)) {
        int m0 = 0, m1 = 0;
#pragma unroll 2
        for (int g = 0; g < 8; g++) {
            float s0, s1;
            row_dots<true>(emb, base + rbase0 + g * 4, a0, a1, sub, s0, s1);
            m0 += (s0 >= thr);
            m1 += (s1 >= thr);
        }
        m0 += __shfl_xor_sync(0xffffffffu, m0, 8);
        m1 += __shfl_xor_sync(0xffffffffu, m1, 8);
        m0 += __shfl_xor_sync(0xffffffffu, m0, 16);
        m1 += __shfl_xor_sync(0xffffffffu, m1, 16);
        if (lane == 0) { atomicAdd(&sc0, m0); atomicAdd(&sc1, m1); }
        __syncthreads();
        c0 = sc0; c1 = sc1;
        __syncthreads();
        base += 256;
    }

    if (tid == 0) {
        double fast = (double)KNEG * (double)fmaxf(D - S0, 0.f);
        double contrib = 0.0;
        if (c0 >= KNEG) contrib += fast;
        if (c1 >= KNEG) contrib += fast;
        atomicAdd(&g_acc, contrib);
        g_D[t] = D;
        if (c0 < KNEG) g_queue[atomicAdd(&g_nfb, 1)] = t;            // side 0
        if (c1 < KNEG) g_queue[atomicAdd(&g_nfb, 1)] = TLINKS + t;   // side 1

        // ---- ticket: last block publishes the result (and resets g_acc) ----
        __threadfence();
        unsigned int old = atomicInc(&g_ticket_hot, TLINKS - 1);  // wraps to 0
        if (old == TLINKS - 1) {
            double total = atomicAdd(&g_acc, 0.0);   // coherent read
            g_partsum = total;
            out[0] = (float)(total / (2.0 * (double)KNEG * (double)TLINKS));
            g_acc = 0.0;                             // ready for next replay
        }
    }
}

// ---------------------------------------------------------------------------
// Fallback guard: if the work queue is empty (always, in practice) every
// block exits immediately — cost is bare kernel launch/exit. Otherwise run
// the exact MSB-first radix select per flagged query, and the last-ticket
// block overwrites out with g_partsum + fbsum and resets the queue state.
__global__ void __launch_bounds__(256) fallback_kernel(const float* __restrict__ emb,
                                                       const float* __restrict__ cptr,
                                                       const void*  __restrict__ links,
                                                       float*       __restrict__ out) {
    const int nfb = g_nfb;   // written by hot_kernel (kernel-boundary visible)
    if (nfb == 0) return;    // uniform: whole grid exits

    const int tid = threadIdx.x;

    __shared__ float        q[DIM];
    __shared__ unsigned int hist[256];
    __shared__ unsigned int s_prefix;
    __shared__ int          s_k;
    __shared__ double       ssum[256];
    __shared__ int          scm[256];
    __shared__ int          s_last;

    for (int qi = blockIdx.x; qi < nfb; qi += FBGRID) {
        const int s    = g_queue[qi];
        const int t    = s % TLINKS;
        const int side = s / TLINKS;

        const float cval = cptr[0];
        const float Kv   = 1.0f / cval;
        const int* links32 = (const int*)links;

        // dtype detection (32 odd-word samples, block-wide OR)
        int mybad = 0;
        if (tid < 32) {
            int idx = t + tid; if (idx >= TLINKS) idx -= TLINKS;
            mybad = (links32[2 * idx + 1] != 0);
        }
        const int is64 = __syncthreads_or(mybad) ? 0 : 1;

        const long long node = is64 ? ((const long long*)links)[2 * t + side]
                                    : (long long)links32[2 * t + side];

        if (tid < DIM) q[tid] = emb[(size_t)node * DIM + tid];
        if (tid == 0) { s_prefix = 0u; s_k = KNEG; }
        __syncthreads();

        const float D = g_D[t];

        for (int pass = 0; pass < 4; pass++) {
            const int shift = 24 - 8 * pass;
            const unsigned int pmask  = (pass == 0) ? 0u : (0xFFFFFFFFu << (shift + 8));
            const unsigned int prefix = s_prefix;
            hist[tid] = 0u;
            __syncthreads();
            for (int j = tid; j < NNODES; j += 256) {
                float v = sqdist_full(q, emb + (size_t)j * DIM, cval, Kv);
                unsigned int b = __float_as_uint(v);
                if ((b & pmask) == prefix)
                    atomicAdd(&hist[(b >> shift) & 0xFFu], 1u);
            }
            __syncthreads();
            if (tid == 0) {
                int k = s_k;
                unsigned int acc = 0;
                int digit = 0;
                for (; digit < 255; digit++) {
                    if (acc + hist[digit] >= (unsigned)k) break;
                    acc += hist[digit];
                }
                s_k      = k - (int)acc;
                s_prefix = prefix | ((unsigned)digit << shift);
            }
            __syncthreads();
        }

        const unsigned int tau_bits = s_prefix;
        const float        tau      = __uint_as_float(tau_bits);

        int    m_local = 0;
        double sum_local = 0.0;
        for (int j = tid; j < NNODES; j += 256) {
            float v = sqdist_full(q, emb + (size_t)j * DIM, cval, Kv);
            if (__float_as_uint(v) < tau_bits) {
                m_local++;
                sum_local += (double)fmaxf(D - v, 0.f);
            }
        }
        ssum[tid] = sum_local;
        scm[tid]  = m_local;
        __syncthreads();
        for (int o = 128; o > 0; o >>= 1) {
            if (tid < o) { ssum[tid] += ssum[tid + o]; scm[tid] += scm[tid + o]; }
            __syncthreads();
        }
        if (tid == 0) {
            int m = scm[0];
            double res = ssum[0] + (double)(KNEG - m) * (double)fmaxf(D - tau, 0.f);
            atomicAdd(&g_fbsum, res);
        }
        __syncthreads();
    }

    // ---- ticket (only reached when nfb > 0): last block finalizes ----
    if (tid == 0) {
        __threadfence();
        unsigned int old = atomicInc(&g_ticket_fb, FBGRID - 1);  // wraps to 0
        s_last = (old == FBGRID - 1);
    }
    __syncthreads();

    if (s_last && tid == 0) {
        __threadfence();
        double total = g_partsum + g_fbsum;
        out[0] = (float)(total / (2.0 * (double)KNEG * (double)TLINKS));
        g_nfb   = 0;      // reset queue state for the next graph replay
        g_fbsum = 0.0;
    }
}

// ---------------------------------------------------------------------------
extern "C" void kernel_launch(void* const* d_in, const int* in_sizes, int n_in,
                              void* d_out, int out_size) {
    const float* emb   = nullptr;
    const float* c     = nullptr;
    const void*  links = nullptr;
    for (int i = 0; i < n_in; i++) {
        if (in_sizes[i] == 1)               c     = (const float*)d_in[i];
        else if (in_sizes[i] == 2 * TLINKS) links = d_in[i];
        else                                emb   = (const float*)d_in[i];
    }

    hot_kernel     <<<TLINKS, 256>>>(emb, c, links, (float*)d_out);
    fallback_kernel<<<FBGRID, 256>>>(emb, c, links, (float*)d_out);
}

// round 15
// speedup vs baseline: 1.9908x; 1.1955x over previous
#include <cuda_runtime.h>
#include <math.h>

#define NNODES 30000
#define DIM    128
#define TLINKS 3000
#define KNEG   75
#define GAMMA  1.0f
#define MAXSQ  50.0f
// float(1.0 + 1e-7) == 0x3F800001 (1 ulp above 1.0f) — matches XLA's f32 cast
#define THETA0 (1.0f + 1e-7f)
#define FBGRID 128

// ---- device scratch (no allocation allowed) ----
__device__ double       g_acc   = 0.0;     // fast-path sum; reset by finalizer
__device__ float        g_D[TLINKS];       // per-link D = sqdist(l,r)+GAMMA
__device__ int          g_queue[2*TLINKS]; // flagged query ids (side*TLINKS+t)
__device__ int          g_nfb   = 0;       // queue length; reset by fb finisher
__device__ double       g_fbsum = 0.0;     // fallback sum;  reset by fb finisher
__device__ unsigned int g_ticket_fb = 0;   // used only when queue non-empty

// ---------------------------------------------------------------------------
__device__ __forceinline__ float sqdist_from_mdot(float mdot, float cval, float Kv) {
    float th = fmaxf(-mdot * cval, THETA0);
    float a  = acoshf(th);
    return fminf(Kv * a * a, MAXSQ);
}

// full 128-dim Minkowski sqdist, one thread (fallback path only)
__device__ __forceinline__ float sqdist_full(const float* __restrict__ q,
                                             const float* __restrict__ row,
                                             float cval, float Kv) {
    float md = 0.f;
#pragma unroll
    for (int d = 0; d < DIM; d++) {
        float p = q[d] * row[d];
        md += (d == 0) ? -p : p;
    }
    return sqdist_from_mdot(md, cval, Kv);
}

// ---------------------------------------------------------------------------
// Per-row dot pair with split accumulators (8-deep FFMA chains).
// Returns via s0/s1 the FULL (sub-group-reduced) dots on every lane.
template <bool GUARD>
__device__ __forceinline__ void row_dots(const float* __restrict__ emb, int row,
                                         const float4* a0, const float4* a1, int sub,
                                         float& s0, float& s1) {
    float s0a = 0.f, s0b = 0.f, s1a = 0.f, s1b = 0.f;
    if (!GUARD || row < NNODES) {
        const float4* p = (const float4*)(emb + (size_t)row * DIM);
        float4 y0 = p[0 * 8 + sub];
        float4 y1 = p[1 * 8 + sub];
        float4 y2 = p[2 * 8 + sub];
        float4 y3 = p[3 * 8 + sub];
        s0a = a0[0].x*y0.x + a0[0].y*y0.y + a0[0].z*y0.z + a0[0].w*y0.w
            + a0[1].x*y1.x + a0[1].y*y1.y + a0[1].z*y1.z + a0[1].w*y1.w;
        s0b = a0[2].x*y2.x + a0[2].y*y2.y + a0[2].z*y2.z + a0[2].w*y2.w
            + a0[3].x*y3.x + a0[3].y*y3.y + a0[3].z*y3.z + a0[3].w*y3.w;
        s1a = a1[0].x*y0.x + a1[0].y*y0.y + a1[0].z*y0.z + a1[0].w*y0.w
            + a1[1].x*y1.x + a1[1].y*y1.y + a1[1].z*y1.z + a1[1].w*y1.w;
        s1b = a1[2].x*y2.x + a1[2].y*y2.y + a1[2].z*y2.z + a1[2].w*y2.w
            + a1[3].x*y3.x + a1[3].y*y3.y + a1[3].z*y3.z + a1[3].w*y3.w;
    } else {
        s0a = -1e30f; s1a = -1e30f;    // guarded-out rows never count
    }
    s0 = s0a + s0b;
    s1 = s1a + s1b;
    s0 += __shfl_xor_sync(0xffffffffu, s0, 1);
    s1 += __shfl_xor_sync(0xffffffffu, s1, 1);
    s0 += __shfl_xor_sync(0xffffffffu, s0, 2);
    s1 += __shfl_xor_sync(0xffffffffu, s1, 2);
    s0 += __shfl_xor_sync(0xffffffffu, s0, 4);
    s1 += __shfl_xor_sync(0xffffffffu, s1, 4);
}

// ---------------------------------------------------------------------------
// HOT kernel: one block (256 threads) per link; 4 blocks/SM.
//  - NO fences, NO tickets, NO reductions here: the kernel boundary to the
//    fallback kernel is the only synchronization needed. Per-block result
//    leaves via ONE relaxed fp64 atomicAdd (atomics bypass L1 — no CCTL.IVALL
//    flush disturbing co-resident blocks' cached emb rows).
//  - is64 detected per-warp (warps 0/1) by a 32-sample ballot over odd int32
//    words (int64 ids < 30000 have all odd words zero).
//  - coalesced candidate reads: lane sub owns float4s j = i*8+sub.
//  - count rows with theta clipped (mdot >= -THETA0/c <=> sqdist == S0);
//    count >= 75  =>  top-75 all exactly S0  =>  75 * relu(D - S0).
//    Else (never in practice): push query onto the fallback work-queue.
__global__ void __launch_bounds__(256, 4) hot_kernel(const float* __restrict__ emb,
                                                     const float* __restrict__ cptr,
                                                     const void*  __restrict__ links) {
    __shared__ float  q[2][DIM];
    __shared__ float  sD;
    __shared__ int    sc0, sc1;

    const int t    = blockIdx.x;
    const int tid  = threadIdx.x;
    const int w    = tid >> 5;
    const int lane = tid & 31;
    const int sub  = lane & 7;          // 8-lane sub-group position

    const float cval = cptr[0];
    const float Kv   = 1.0f / cval;

    // warps 0/1: detect dtype, fetch own node, stage its q row (float4)
    if (w < 2) {
        const int* links32 = (const int*)links;
        int idx = t + lane; if (idx >= TLINKS) idx -= TLINKS;
        unsigned nz = __ballot_sync(0xffffffffu, links32[2 * idx + 1] != 0);
        const int is64 = (nz == 0);
        long long node = is64 ? ((const long long*)links)[2 * t + w]
                              : (long long)links32[2 * t + w];
        ((float4*)q[w])[lane] = ((const float4*)(emb + (size_t)node * DIM))[lane];
    }
    if (tid == 0) { sc0 = 0; sc1 = 0; }
    __syncthreads();

    // per-lane register slices, mapping j = i*8 + sub (dim 0 is i=0,sub=0,.x)
    float4 a0[4], a1[4];
#pragma unroll
    for (int i = 0; i < 4; i++) {
        a0[i] = ((const float4*)q[0])[i * 8 + sub];
        a1[i] = ((const float4*)q[1])[i * 8 + sub];
    }
    if (sub == 0) { a0[0].x = -a0[0].x; a1[0].x = -a1[0].x; }

    // D = sqdist(left,right) + GAMMA  (sign-folded a0 vs RAW q1)
    if (w == 0) {
        float s = 0.f;
#pragma unroll
        for (int i = 0; i < 4; i++) {
            float4 b = ((const float4*)q[1])[i * 8 + sub];
            s += a0[i].x * b.x + a0[i].y * b.y + a0[i].z * b.z + a0[i].w * b.w;
        }
        s += __shfl_xor_sync(0xffffffffu, s, 1);
        s += __shfl_xor_sync(0xffffffffu, s, 2);
        s += __shfl_xor_sync(0xffffffffu, s, 4);
        if (tid == 0) sD = sqdist_from_mdot(s, cval, Kv) + GAMMA;
    }
    __syncthreads();
    const float D = sD;

    float acz = acoshf(THETA0);
    const float S0  = fminf(Kv * acz * acz, MAXSQ);
    const float thr = -(THETA0 * Kv);    // mdot >= thr  <=>  theta clips to 1+EPS

    const int rbase0 = (w << 5) + (lane >> 3);
    int l0 = 0, l1 = 0;

    // ---- chunk 0: rows 0..255, no bounds guard (256 << NNODES) ----
#pragma unroll 4
    for (int g = 0; g < 8; g++) {
        float s0, s1;
        row_dots<false>(emb, rbase0 + g * 4, a0, a1, sub, s0, s1);
        l0 += (s0 >= thr);
        l1 += (s1 >= thr);
    }
    // xor8 + xor16 -> exact warp count on every lane.
    l0 += __shfl_xor_sync(0xffffffffu, l0, 8);
    l1 += __shfl_xor_sync(0xffffffffu, l1, 8);
    l0 += __shfl_xor_sync(0xffffffffu, l0, 16);
    l1 += __shfl_xor_sync(0xffffffffu, l1, 16);
    if (lane == 0) { atomicAdd(&sc0, l0); atomicAdd(&sc1, l1); }
    __syncthreads();
    int c0 = sc0, c1 = sc1;
    __syncthreads();

    // ---- rare continuation: more chunks until both counts reach 75 ----
    int base = 256;
    while (base < NNODES && (c0 < KNEG || c1 < KNEG)) {
        int m0 = 0, m1 = 0;
#pragma unroll 2
        for (int g = 0; g < 8; g++) {
            float s0, s1;
            row_dots<true>(emb, base + rbase0 + g * 4, a0, a1, sub, s0, s1);
            m0 += (s0 >= thr);
            m1 += (s1 >= thr);
        }
        m0 += __shfl_xor_sync(0xffffffffu, m0, 8);
        m1 += __shfl_xor_sync(0xffffffffu, m1, 8);
        m0 += __shfl_xor_sync(0xffffffffu, m0, 16);
        m1 += __shfl_xor_sync(0xffffffffu, m1, 16);
        if (lane == 0) { atomicAdd(&sc0, m0); atomicAdd(&sc1, m1); }
        __syncthreads();
        c0 = sc0; c1 = sc1;
        __syncthreads();
        base += 256;
    }

    if (tid == 0) {
        double fast = (double)KNEG * (double)fmaxf(D - S0, 0.f);
        double contrib = 0.0;
        if (c0 >= KNEG) contrib += fast;
        if (c1 >= KNEG) contrib += fast;
        atomicAdd(&g_acc, contrib);          // relaxed; L2-coherent, no L1 flush
        g_D[t] = D;
        if (c0 < KNEG) g_queue[atomicAdd(&g_nfb, 1)] = t;            // side 0
        if (c1 < KNEG) g_queue[atomicAdd(&g_nfb, 1)] = TLINKS + t;   // side 1
    }
}

// ---------------------------------------------------------------------------
// Fallback + finalize. The kernel-launch boundary makes all hot-kernel
// writes visible. Empty-queue path (always, in practice): block 0 / tid 0
// publishes g_acc and resets it; every other block exits immediately.
// Non-empty path: exact MSB-first radix select per flagged query, then the
// last-ticket block publishes g_acc + g_fbsum and resets all state.
__global__ void __launch_bounds__(256) fallback_kernel(const float* __restrict__ emb,
                                                       const float* __restrict__ cptr,
                                                       const void*  __restrict__ links,
                                                       float*       __restrict__ out) {
    const int nfb = g_nfb;   // written by hot_kernel (kernel-boundary visible)

    if (nfb == 0) {
        if (blockIdx.x == 0 && threadIdx.x == 0) {
            double total = g_acc;
            out[0] = (float)(total / (2.0 * (double)KNEG * (double)TLINKS));
            g_acc = 0.0;                     // ready for next graph replay
        }
        return;
    }

    const int tid = threadIdx.x;

    __shared__ float        q[DIM];
    __shared__ unsigned int hist[256];
    __shared__ unsigned int s_prefix;
    __shared__ int          s_k;
    __shared__ double       ssum[256];
    __shared__ int          scm[256];
    __shared__ int          s_last;

    for (int qi = blockIdx.x; qi < nfb; qi += FBGRID) {
        const int s    = g_queue[qi];
        const int t    = s % TLINKS;
        const int side = s / TLINKS;

        const float cval = cptr[0];
        const float Kv   = 1.0f / cval;
        const int* links32 = (const int*)links;

        // dtype detection (32 odd-word samples, block-wide OR)
        int mybad = 0;
        if (tid < 32) {
            int idx = t + tid; if (idx >= TLINKS) idx -= TLINKS;
            mybad = (links32[2 * idx + 1] != 0);
        }
        const int is64 = __syncthreads_or(mybad) ? 0 : 1;

        const long long node = is64 ? ((const long long*)links)[2 * t + side]
                                    : (long long)links32[2 * t + side];

        if (tid < DIM) q[tid] = emb[(size_t)node * DIM + tid];
        if (tid == 0) { s_prefix = 0u; s_k = KNEG; }
        __syncthreads();

        const float D = g_D[t];

        for (int pass = 0; pass < 4; pass++) {
            const int shift = 24 - 8 * pass;
            const unsigned int pmask  = (pass == 0) ? 0u : (0xFFFFFFFFu << (shift + 8));
            const unsigned int prefix = s_prefix;
            hist[tid] = 0u;
            __syncthreads();
            for (int j = tid; j < NNODES; j += 256) {
                float v = sqdist_full(q, emb + (size_t)j * DIM, cval, Kv);
                unsigned int b = __float_as_uint(v);
                if ((b & pmask) == prefix)
                    atomicAdd(&hist[(b >> shift) & 0xFFu], 1u);
            }
            __syncthreads();
            if (tid == 0) {
                int k = s_k;
                unsigned int acc = 0;
                int digit = 0;
                for (; digit < 255; digit++) {
                    if (acc + hist[digit] >= (unsigned)k) break;
                    acc += hist[digit];
                }
                s_k      = k - (int)acc;
                s_prefix = prefix | ((unsigned)digit << shift);
            }
            __syncthreads();
        }

        const unsigned int tau_bits = s_prefix;
        const float        tau      = __uint_as_float(tau_bits);

        int    m_local = 0;
        double sum_local = 0.0;
        for (int j = tid; j < NNODES; j += 256) {
            float v = sqdist_full(q, emb + (size_t)j * DIM, cval, Kv);
            if (__float_as_uint(v) < tau_bits) {
                m_local++;
                sum_local += (double)fmaxf(D - v, 0.f);
            }
        }
        ssum[tid] = sum_local;
        scm[tid]  = m_local;
        __syncthreads();
        for (int o = 128; o > 0; o >>= 1) {
            if (tid < o) { ssum[tid] += ssum[tid + o]; scm[tid] += scm[tid + o]; }
            __syncthreads();
        }
        if (tid == 0) {
            int m = scm[0];
            double res = ssum[0] + (double)(KNEG - m) * (double)fmaxf(D - tau, 0.f);
            atomicAdd(&g_fbsum, res);
        }
        __syncthreads();
    }

    // ---- ticket (only reached when nfb > 0): last block finalizes ----
    if (tid == 0) {
        __threadfence();
        unsigned int old = atomicInc(&g_ticket_fb, FBGRID - 1);  // wraps to 0
        s_last = (old == FBGRID - 1);
    }
    __syncthreads();

    if (s_last && tid == 0) {
        __threadfence();
        double total = g_acc + g_fbsum;
        out[0] = (float)(total / (2.0 * (double)KNEG * (double)TLINKS));
        g_acc   = 0.0;    // reset all state for the next graph replay
        g_nfb   = 0;
        g_fbsum = 0.0;
    }
}

// ---------------------------------------------------------------------------
extern "C" void kernel_launch(void* const* d_in, const int* in_sizes, int n_in,
                              void* d_out, int out_size) {
    const float* emb   = nullptr;
    const float* c     = nullptr;
    const void*  links = nullptr;
    for (int i = 0; i < n_in; i++) {
        if (in_sizes[i] == 1)               c     = (const float*)d_in[i];
        else if (in_sizes[i] == 2 * TLINKS) links = d_in[i];
        else                                emb   = (const float*)d_in[i];
    }

    hot_kernel     <<<TLINKS, 256>>>(emb, c, links);
    fallback_kernel<<<FBGRID, 256>>>(emb, c, links, (float*)d_out);
}

// round 16
// speedup vs baseline: 1.9928x; 1.0010x over previous
#include <cuda_runtime.h>
#include <math.h>

#define NNODES 30000
#define DIM    128
#define TLINKS 3000
#define KNEG   75
#define GAMMA  1.0f
#define MAXSQ  50.0f
// float(1.0 + 1e-7) == 0x3F800001 (1 ulp above 1.0f) — matches XLA's f32 cast
#define THETA0 (1.0f + 1e-7f)
#define FBGRID 128

typedef unsigned long long u64;

// ---- device scratch (no allocation allowed) ----
__device__ double       g_acc   = 0.0;     // fast-path sum; reset by finalizer
__device__ float        g_D[TLINKS];       // per-link D = sqdist(l,r)+GAMMA
__device__ int          g_queue[2*TLINKS]; // flagged query ids (side*TLINKS+t)
__device__ int          g_nfb   = 0;       // queue length; reset by fb finisher
__device__ double       g_fbsum = 0.0;     // fallback sum;  reset by fb finisher
__device__ unsigned int g_ticket_fb = 0;   // used only when queue non-empty

// ---------------------------------------------------------------------------
__device__ __forceinline__ float sqdist_from_mdot(float mdot, float cval, float Kv) {
    float th = fmaxf(-mdot * cval, THETA0);
    float a  = acoshf(th);
    return fminf(Kv * a * a, MAXSQ);
}

// full 128-dim Minkowski sqdist, one thread (fallback path only)
__device__ __forceinline__ float sqdist_full(const float* __restrict__ q,
                                             const float* __restrict__ row,
                                             float cval, float Kv) {
    float md = 0.f;
#pragma unroll
    for (int d = 0; d < DIM; d++) {
        float p = q[d] * row[d];
        md += (d == 0) ? -p : p;
    }
    return sqdist_from_mdot(md, cval, Kv);
}

// ---- packed 2xf32 helpers (sm_103a FFMA2 path; PTX-only) ----
__device__ __forceinline__ u64 pack_f2(float lo, float hi) {
    u64 r;
    asm("mov.b64 %0, {%1, %2};" : "=l"(r)
        : "r"(__float_as_uint(lo)), "r"(__float_as_uint(hi)));
    return r;
}
__device__ __forceinline__ float unpack_sum(u64 v) {
    unsigned int lo, hi;
    asm("mov.b64 {%0, %1}, %2;" : "=r"(lo), "=r"(hi) : "l"(v));
    return __uint_as_float(lo) + __uint_as_float(hi);
}
__device__ __forceinline__ void ffma2(u64& d, u64 a, u64 b) {
    asm("fma.rn.f32x2 %0, %1, %2, %0;" : "+l"(d) : "l"(a), "l"(b));
}
__device__ __forceinline__ u64 fadd2(u64 a, u64 b) {
    u64 r;
    asm("add.rn.f32x2 %0, %1, %2;" : "=l"(r) : "l"(a), "l"(b));
    return r;
}

// ---------------------------------------------------------------------------
// Per-row dot pair, packed f32x2 math (16 FFMA2 instead of 32 FFMA).
// aq0/aq1: 8 packed u64 per lane (16 dims), dim-0 sign pre-folded.
// Returns via s0/s1 the FULL (sub-group-reduced) dots on every lane.
template <bool GUARD>
__device__ __forceinline__ void row_dots(const float* __restrict__ emb, int row,
                                         const u64* aq0, const u64* aq1, int sub,
                                         float& s0, float& s1) {
    if (!GUARD || row < NNODES) {
        const float4* p = (const float4*)(emb + (size_t)row * DIM);
        u64 acc0a = 0ull, acc0b = 0ull, acc1a = 0ull, acc1b = 0ull;  // {0f,0f}
#pragma unroll
        for (int i = 0; i < 4; i++) {
            float4 y = p[i * 8 + sub];              // one LDG.128, coalesced
            u64 ylo = pack_f2(y.x, y.y);            // register-pair aliasing
            u64 yhi = pack_f2(y.z, y.w);
            ffma2(acc0a, aq0[2 * i],     ylo);
            ffma2(acc0b, aq0[2 * i + 1], yhi);
            ffma2(acc1a, aq1[2 * i],     ylo);
            ffma2(acc1b, aq1[2 * i + 1], yhi);
        }
        s0 = unpack_sum(fadd2(acc0a, acc0b));
        s1 = unpack_sum(fadd2(acc1a, acc1b));
    } else {
        s0 = -1e30f; s1 = -1e30f;    // guarded-out rows never count
    }
    s0 += __shfl_xor_sync(0xffffffffu, s0, 1);
    s1 += __shfl_xor_sync(0xffffffffu, s1, 1);
    s0 += __shfl_xor_sync(0xffffffffu, s0, 2);
    s1 += __shfl_xor_sync(0xffffffffu, s1, 2);
    s0 += __shfl_xor_sync(0xffffffffu, s0, 4);
    s1 += __shfl_xor_sync(0xffffffffu, s1, 4);
}

// ---------------------------------------------------------------------------
// HOT kernel: one block (256 threads) per link; 4 blocks/SM.
//  - NO fences/tickets/reductions (kernel boundary is the sync; one relaxed
//    fp64 atomicAdd per block, bypasses L1 so no CCTL.IVALL flush).
//  - is64 detected per-warp by a 32-sample ballot over odd int32 words.
//  - coalesced candidate reads: lane sub owns float4s j = i*8+sub.
//  - count rows with theta clipped (mdot >= -THETA0/c <=> sqdist == S0);
//    count >= 75  =>  top-75 all exactly S0  =>  75 * relu(D - S0).
//    Else (never in practice): push query onto the fallback work-queue.
__global__ void __launch_bounds__(256, 4) hot_kernel(const float* __restrict__ emb,
                                                     const float* __restrict__ cptr,
                                                     const void*  __restrict__ links) {
    __shared__ float  q[2][DIM];
    __shared__ float  sD;
    __shared__ int    sc0, sc1;

    const int t    = blockIdx.x;
    const int tid  = threadIdx.x;
    const int w    = tid >> 5;
    const int lane = tid & 31;
    const int sub  = lane & 7;          // 8-lane sub-group position

    const float cval = cptr[0];
    const float Kv   = 1.0f / cval;

    // warps 0/1: detect dtype, fetch own node, stage its q row (float4)
    if (w < 2) {
        const int* links32 = (const int*)links;
        int idx = t + lane; if (idx >= TLINKS) idx -= TLINKS;
        unsigned nz = __ballot_sync(0xffffffffu, links32[2 * idx + 1] != 0);
        const int is64 = (nz == 0);
        long long node = is64 ? ((const long long*)links)[2 * t + w]
                              : (long long)links32[2 * t + w];
        ((float4*)q[w])[lane] = ((const float4*)(emb + (size_t)node * DIM))[lane];
    }
    if (tid == 0) { sc0 = 0; sc1 = 0; }
    __syncthreads();

    // per-lane PACKED query slices: 8 u64 each (16 dims), j = i*8 + sub.
    // dim 0 lives in the low word of aq[0] for sub==0 — flip its sign bit.
    u64 aq0[8], aq1[8];
    {
        const u64* q0p = (const u64*)q[0];
        const u64* q1p = (const u64*)q[1];
#pragma unroll
        for (int i = 0; i < 4; i++) {
            aq0[2 * i]     = q0p[(i * 8 + sub) * 2];
            aq0[2 * i + 1] = q0p[(i * 8 + sub) * 2 + 1];
            aq1[2 * i]     = q1p[(i * 8 + sub) * 2];
            aq1[2 * i + 1] = q1p[(i * 8 + sub) * 2 + 1];
        }
    }
    if (sub == 0) { aq0[0] ^= 0x80000000ull; aq1[0] ^= 0x80000000ull; }

    // D = sqdist(left,right) + GAMMA  (scalar, cold; sign via explicit negate)
    if (w == 0) {
        float s = 0.f;
#pragma unroll
        for (int i = 0; i < 4; i++) {
            float4 a = ((const float4*)q[0])[i * 8 + sub];
            float4 b = ((const float4*)q[1])[i * 8 + sub];
            if (i == 0 && sub == 0) a.x = -a.x;
            s += a.x * b.x + a.y * b.y + a.z * b.z + a.w * b.w;
        }
        s += __shfl_xor_sync(0xffffffffu, s, 1);
        s += __shfl_xor_sync(0xffffffffu, s, 2);
        s += __shfl_xor_sync(0xffffffffu, s, 4);
        if (tid == 0) sD = sqdist_from_mdot(s, cval, Kv) + GAMMA;
    }
    __syncthreads();
    const float D = sD;

    float acz = acoshf(THETA0);
    const float S0  = fminf(Kv * acz * acz, MAXSQ);
    const float thr = -(THETA0 * Kv);    // mdot >= thr  <=>  theta clips to 1+EPS

    const int rbase0 = (w << 5) + (lane >> 3);
    int l0 = 0, l1 = 0;

    // ---- chunk 0: rows 0..255, no bounds guard (256 << NNODES) ----
#pragma unroll 4
    for (int g = 0; g < 8; g++) {
        float s0, s1;
        row_dots<false>(emb, rbase0 + g * 4, aq0, aq1, sub, s0, s1);
        l0 += (s0 >= thr);
        l1 += (s1 >= thr);
    }
    // xor8 + xor16 -> exact warp count on every lane.
    l0 += __shfl_xor_sync(0xffffffffu, l0, 8);
    l1 += __shfl_xor_sync(0xffffffffu, l1, 8);
    l0 += __shfl_xor_sync(0xffffffffu, l0, 16);
    l1 += __shfl_xor_sync(0xffffffffu, l1, 16);
    if (lane == 0) { atomicAdd(&sc0, l0); atomicAdd(&sc1, l1); }
    __syncthreads();
    int c0 = sc0, c1 = sc1;
    __syncthreads();

    // ---- rare continuation: more chunks until both counts reach 75 ----
    int base = 256;
    while (base < NNODES && (c0 < KNEG || c1 < KNEG)) {
        int m0 = 0, m1 = 0;
#pragma unroll 2
        for (int g = 0; g < 8; g++) {
            float s0, s1;
            row_dots<true>(emb, base + rbase0 + g * 4, aq0, aq1, sub, s0, s1);
            m0 += (s0 >= thr);
            m1 += (s1 >= thr);
        }
        m0 += __shfl_xor_sync(0xffffffffu, m0, 8);
        m1 += __shfl_xor_sync(0xffffffffu, m1, 8);
        m0 += __shfl_xor_sync(0xffffffffu, m0, 16);
        m1 += __shfl_xor_sync(0xffffffffu, m1, 16);
        if (lane == 0) { atomicAdd(&sc0, m0); atomicAdd(&sc1, m1); }
        __syncthreads();
        c0 = sc0; c1 = sc1;
        __syncthreads();
        base += 256;
    }

    if (tid == 0) {
        double fast = (double)KNEG * (double)fmaxf(D - S0, 0.f);
        double contrib = 0.0;
        if (c0 >= KNEG) contrib += fast;
        if (c1 >= KNEG) contrib += fast;
        atomicAdd(&g_acc, contrib);          // relaxed; L2-coherent, no L1 flush
        g_D[t] = D;
        if (c0 < KNEG) g_queue[atomicAdd(&g_nfb, 1)] = t;            // side 0
        if (c1 < KNEG) g_queue[atomicAdd(&g_nfb, 1)] = TLINKS + t;   // side 1
    }
}

// ---------------------------------------------------------------------------
// Fallback + finalize. The kernel-launch boundary makes all hot-kernel
// writes visible. Empty-queue path (always, in practice): block 0 / tid 0
// publishes g_acc and resets it; every other block exits immediately.
// Non-empty path: exact MSB-first radix select per flagged query, then the
// last-ticket block publishes g_acc + g_fbsum and resets all state.
__global__ void __launch_bounds__(256) fallback_kernel(const float* __restrict__ emb,
                                                       const float* __restrict__ cptr,
                                                       const void*  __restrict__ links,
                                                       float*       __restrict__ out) {
    const int nfb = g_nfb;   // written by hot_kernel (kernel-boundary visible)

    if (nfb == 0) {
        if (blockIdx.x == 0 && threadIdx.x == 0) {
            double total = g_acc;
            out[0] = (float)(total / (2.0 * (double)KNEG * (double)TLINKS));
            g_acc = 0.0;                     // ready for next graph replay
        }
        return;
    }

    const int tid = threadIdx.x;

    __shared__ float        q[DIM];
    __shared__ unsigned int hist[256];
    __shared__ unsigned int s_prefix;
    __shared__ int          s_k;
    __shared__ double       ssum[256];
    __shared__ int          scm[256];
    __shared__ int          s_last;

    for (int qi = blockIdx.x; qi < nfb; qi += FBGRID) {
        const int s    = g_queue[qi];
        const int t    = s % TLINKS;
        const int side = s / TLINKS;

        const float cval = cptr[0];
        const float Kv   = 1.0f / cval;
        const int* links32 = (const int*)links;

        // dtype detection (32 odd-word samples, block-wide OR)
        int mybad = 0;
        if (tid < 32) {
            int idx = t + tid; if (idx >= TLINKS) idx -= TLINKS;
            mybad = (links32[2 * idx + 1] != 0);
        }
        const int is64 = __syncthreads_or(mybad) ? 0 : 1;

        const long long node = is64 ? ((const long long*)links)[2 * t + side]
                                    : (long long)links32[2 * t + side];

        if (tid < DIM) q[tid] = emb[(size_t)node * DIM + tid];
        if (tid == 0) { s_prefix = 0u; s_k = KNEG; }
        __syncthreads();

        const float D = g_D[t];

        for (int pass = 0; pass < 4; pass++) {
            const int shift = 24 - 8 * pass;
            const unsigned int pmask  = (pass == 0) ? 0u : (0xFFFFFFFFu << (shift + 8));
            const unsigned int prefix = s_prefix;
            hist[tid] = 0u;
            __syncthreads();
            for (int j = tid; j < NNODES; j += 256) {
                float v = sqdist_full(q, emb + (size_t)j * DIM, cval, Kv);
                unsigned int b = __float_as_uint(v);
                if ((b & pmask) == prefix)
                    atomicAdd(&hist[(b >> shift) & 0xFFu], 1u);
            }
            __syncthreads();
            if (tid == 0) {
                int k = s_k;
                unsigned int acc = 0;
                int digit = 0;
                for (; digit < 255; digit++) {
                    if (acc + hist[digit] >= (unsigned)k) break;
                    acc += hist[digit];
                }
                s_k      = k - (int)acc;
                s_prefix = prefix | ((unsigned)digit << shift);
            }
            __syncthreads();
        }

        const unsigned int tau_bits = s_prefix;
        const float        tau      = __uint_as_float(tau_bits);

        int    m_local = 0;
        double sum_local = 0.0;
        for (int j = tid; j < NNODES; j += 256) {
            float v = sqdist_full(q, emb + (size_t)j * DIM, cval, Kv);
            if (__float_as_uint(v) < tau_bits) {
                m_local++;
                sum_local += (double)fmaxf(D - v, 0.f);
            }
        }
        ssum[tid] = sum_local;
        scm[tid]  = m_local;
        __syncthreads();
        for (int o = 128; o > 0; o >>= 1) {
            if (tid < o) { ssum[tid] += ssum[tid + o]; scm[tid] += scm[tid + o]; }
            __syncthreads();
        }
        if (tid == 0) {
            int m = scm[0];
            double res = ssum[0] + (double)(KNEG - m) * (double)fmaxf(D - tau, 0.f);
            atomicAdd(&g_fbsum, res);
        }
        __syncthreads();
    }

    // ---- ticket (only reached when nfb > 0): last block finalizes ----
    if (tid == 0) {
        __threadfence();
        unsigned int old = atomicInc(&g_ticket_fb, FBGRID - 1);  // wraps to 0
        s_last = (old == FBGRID - 1);
    }
    __syncthreads();

    if (s_last && tid == 0) {
        __threadfence();
        double total = g_acc + g_fbsum;
        out[0] = (float)(total / (2.0 * (double)KNEG * (double)TLINKS));
        g_acc   = 0.0;    // reset all state for the next graph replay
        g_nfb   = 0;
        g_fbsum = 0.0;
    }
}

// ---------------------------------------------------------------------------
extern "C" void kernel_launch(void* const* d_in, const int* in_sizes, int n_in,
                              void* d_out, int out_size) {
    const float* emb   = nullptr;
    const float* c     = nullptr;
    const void*  links = nullptr;
    for (int i = 0; i < n_in; i++) {
        if (in_sizes[i] == 1)               c     = (const float*)d_in[i];
        else if (in_sizes[i] == 2 * TLINKS) links = d_in[i];
        else                                emb   = (const float*)d_in[i];
    }

    hot_kernel     <<<TLINKS, 256>>>(emb, c, links);
    fallback_kernel<<<FBGRID, 256>>>(emb, c, links, (float*)d_out);
}